// round 2
// baseline (speedup 1.0000x reference)
#include <cuda_runtime.h>
#include <cstdint>

#define DEV __device__ __forceinline__

// ---------------- problem constants ----------------
static constexpr int BATCH = 32768;
static constexpr int DH    = 512;          // hidden per gate
static constexpr int KTOT  = 1024;         // D_IN + D_H
static constexpr int MT    = 128;          // rows per CTA
static constexpr int WG    = 64;           // hidden cols per CTA (per gate) -> N_cta = 256
static constexpr int KC    = 32;           // K chunk
static constexpr int NCHUNK = KTOT / KC;   // 32
static constexpr int THREADS = 256;

// smem pitches (words). PA % 32 == 4 and PB % 32 == 8 make fragment LDS conflict-free.
static constexpr int PA = 36;              // A row pitch: [128 rows][KC cols]
static constexpr int PB = 264;             // B row pitch: [KC rows][256 cols]
static constexpr int A_STAGE_B = MT * PA * 4;          // 18432
static constexpr int B_STAGE_B = KC * PB * 4;          // 33792
static constexpr uint32_t OFF_A0 = 0;
static constexpr uint32_t OFF_A1 = A_STAGE_B;
static constexpr uint32_t OFF_B0 = 2 * A_STAGE_B;
static constexpr uint32_t OFF_B1 = 2 * A_STAGE_B + B_STAGE_B;
static constexpr uint32_t OFF_BIAS = 2 * A_STAGE_B + 2 * B_STAGE_B;   // 256 floats
static constexpr uint32_t SMEM_BYTES = OFF_BIAS + 256 * 4;

// ---------------- device scratch ----------------
__device__ float g_Wt[KTOT * 4 * DH];      // [1024 k][2048 n], tf32-rna rounded

// ---------------- PTX helpers ----------------
DEV uint32_t smem_u32(const void* p) {
    uint32_t a;
    asm("{ .reg .u64 t; cvta.to.shared.u64 t, %1; cvt.u32.u64 %0, t; }" : "=r"(a) : "l"(p));
    return a;
}
DEV float tf32_rna(float v) {
    uint32_t u;
    asm("cvt.rna.tf32.f32 %0, %1;" : "=r"(u) : "f"(v));
    return __uint_as_float(u);
}
DEV void cpasync16(uint32_t dst, const void* src) {
    asm volatile("cp.async.cg.shared.global [%0], [%1], 16;" :: "r"(dst), "l"(src));
}
DEV void cp_commit() { asm volatile("cp.async.commit_group;" ::: "memory"); }
template <int N> DEV void cp_wait() { asm volatile("cp.async.wait_group %0;" :: "n"(N) : "memory"); }

DEV void mma_tf32(float* c, const uint32_t* a, const uint32_t* b) {
    asm volatile(
        "mma.sync.aligned.m16n8k8.row.col.f32.tf32.tf32.f32 "
        "{%0,%1,%2,%3}, {%4,%5,%6,%7}, {%8,%9}, {%0,%1,%2,%3};"
        : "+f"(c[0]), "+f"(c[1]), "+f"(c[2]), "+f"(c[3])
        : "r"(a[0]), "r"(a[1]), "r"(a[2]), "r"(a[3]), "r"(b[0]), "r"(b[1]));
}

DEV float sigm(float z)     { return __fdividef(1.0f, 1.0f + __expf(-z)); }
DEV float tanhfast(float z) { float t = __expf(2.0f * z); return 1.0f - __fdividef(2.0f, t + 1.0f); }

// ---------------- prep: concat + tf32-round weights (layout stays [k][2048]) ----------------
__global__ void lstm_prep(const float* __restrict__ Wx, const float* __restrict__ Wh) {
    const int total4 = KTOT * 4 * DH / 4;
    for (int i = blockIdx.x * blockDim.x + threadIdx.x; i < total4; i += gridDim.x * blockDim.x) {
        int k = i >> 9;                  // i*4 / 2048
        const float4 v = (k < 512) ? *(const float4*)(Wx + (size_t)i * 4)
                                   : *(const float4*)(Wh + (size_t)(i - 512 * 512) * 4);
        float4 r;
        r.x = tf32_rna(v.x); r.y = tf32_rna(v.y); r.z = tf32_rna(v.z); r.w = tf32_rna(v.w);
        *(float4*)(g_Wt + (size_t)i * 4) = r;
    }
}

// ---------------- main fused kernel ----------------
__global__ __launch_bounds__(THREADS, 1)
void lstm_main(const float* __restrict__ x, const float* __restrict__ Cin,
               const float* __restrict__ h,
               const float* __restrict__ bx, const float* __restrict__ bh,
               float* __restrict__ out) {
    extern __shared__ float smem[];
    const uint32_t sb = smem_u32(smem);

    const int tid  = threadIdx.x;
    const int lane = tid & 31;
    const int wid  = tid >> 5;
    const int tig  = lane & 3;          // thread-in-group (k / col*2)
    const int gid  = lane >> 2;         // group id (row / col)
    const int wm   = wid >> 2;          // 0..1  (M warp)
    const int wn   = wid & 3;           // 0..3  (N warp)

    const int c0 = blockIdx.x * WG;     // hidden-col base (per gate)
    const int m0 = blockIdx.y * MT;     // row base

    // bias: smem[OFF_BIAS/4 + gate*64 + c] = bx + bh
    {
        int gate = tid >> 6, c = tid & 63;
        int n = gate * DH + c0 + c;
        smem[OFF_BIAS / 4 + tid] = bx[n] + bh[n];
    }

    const uint32_t Aoff[2] = { sb + OFF_A0, sb + OFF_A1 };
    const uint32_t Boff[2] = { sb + OFF_B0, sb + OFF_B1 };

    // ---- async stage loader ----
    auto issue = [&](int ck, int buf) {
        const int kc0 = ck * KC;
        const float* Abase = (kc0 < 512) ? (x + (size_t)m0 * 512 + kc0)
                                         : (h + (size_t)m0 * 512 + (kc0 - 512));
#pragma unroll
        for (int i = 0; i < 4; i++) {                    // A: 128 rows x 8 x 16B
            int f = tid + i * THREADS;
            int r = f >> 3, j = f & 7;
            cpasync16(Aoff[buf] + (uint32_t)(r * PA * 4 + j * 16),
                      Abase + (size_t)r * 512 + j * 4);
        }
#pragma unroll
        for (int i = 0; i < 8; i++) {                    // B: 32 krows x 4 gates x 16 x 16B
            int f = tid + i * THREADS;
            int kr = f >> 6, j = f & 63;
            int gate = j >> 4, jj = j & 15;
            cpasync16(Boff[buf] + (uint32_t)(kr * PB * 4 + gate * 256 + jj * 16),
                      g_Wt + (size_t)(kc0 + kr) * 2048 + gate * 512 + c0 + jj * 4);
        }
    };

    float acc[4][4][2][4];               // [mf][gate][half][reg]
#pragma unroll
    for (int a = 0; a < 4; a++)
#pragma unroll
        for (int b = 0; b < 4; b++)
#pragma unroll
            for (int hh = 0; hh < 2; hh++)
#pragma unroll
                for (int r = 0; r < 4; r++) acc[a][b][hh][r] = 0.0f;

    issue(0, 0); cp_commit();
    issue(1, 1); cp_commit();

    const float* As[2] = { smem + OFF_A0 / 4, smem + OFF_A1 / 4 };
    const float* Bs[2] = { smem + OFF_B0 / 4, smem + OFF_B1 / 4 };

    for (int ck = 0; ck < NCHUNK; ck++) {
        const int buf = ck & 1;
        cp_wait<1>();
        __syncthreads();

        const float* Ab = As[buf];
        const float* Bb = Bs[buf];
#pragma unroll
        for (int s = 0; s < 4; s++) {                    // 4 x k8 steps
            uint32_t afr[4][4];
#pragma unroll
            for (int mf = 0; mf < 4; mf++) {
                int row = wm * 64 + mf * 16 + gid;
                int k   = s * 8 + tig;
                afr[mf][0] = __float_as_uint(Ab[row * PA + k]);
                afr[mf][1] = __float_as_uint(Ab[(row + 8) * PA + k]);
                afr[mf][2] = __float_as_uint(Ab[row * PA + k + 4]);
                afr[mf][3] = __float_as_uint(Ab[(row + 8) * PA + k + 4]);
            }
            uint32_t bfr[4][2][2];
#pragma unroll
            for (int gate = 0; gate < 4; gate++)
#pragma unroll
                for (int hh = 0; hh < 2; hh++) {
                    int col = gate * 64 + wn * 16 + hh * 8 + gid;
                    int k   = s * 8 + tig;
                    bfr[gate][hh][0] = __float_as_uint(Bb[k * PB + col]);
                    bfr[gate][hh][1] = __float_as_uint(Bb[(k + 4) * PB + col]);
                }
#pragma unroll
            for (int mf = 0; mf < 4; mf++)
#pragma unroll
                for (int gate = 0; gate < 4; gate++)
#pragma unroll
                    for (int hh = 0; hh < 2; hh++)
                        mma_tf32(acc[mf][gate][hh], afr[mf], bfr[gate][hh]);
        }
        __syncthreads();
        if (ck + 2 < NCHUNK) issue(ck + 2, buf);
        cp_commit();
    }

    // ---------------- fused LSTM epilogue ----------------
    const float* biasS = smem + OFF_BIAS / 4;
#pragma unroll
    for (int mf = 0; mf < 4; mf++) {
#pragma unroll
        for (int rh = 0; rh < 2; rh++) {
            const int row = m0 + wm * 64 + mf * 16 + gid + rh * 8;
#pragma unroll
            for (int hh = 0; hh < 2; hh++) {
                const int cl = wn * 16 + hh * 8 + tig * 2;   // local col (0..63)
                const int c  = c0 + cl;
                const float2 cv = *(const float2*)(Cin + (size_t)row * DH + c);
                float cn[2], hn[2];
#pragma unroll
                for (int e = 0; e < 2; e++) {
                    float zi = acc[mf][0][hh][rh * 2 + e] + biasS[0 * 64 + cl + e];
                    float zf = acc[mf][1][hh][rh * 2 + e] + biasS[1 * 64 + cl + e];
                    float zo = acc[mf][2][hh][rh * 2 + e] + biasS[2 * 64 + cl + e];
                    float zg = acc[mf][3][hh][rh * 2 + e] + biasS[3 * 64 + cl + e];
                    float gi = sigm(zi), gf = sigm(zf), go = sigm(zo), gg = tanhfast(zg);
                    float cc = (e == 0) ? cv.x : cv.y;
                    cn[e] = gf * cc + gi * gg;
                    hn[e] = go * tanhfast(cn[e]);
                }
                *(float2*)(out + (size_t)row * DH + c) = make_float2(cn[0], cn[1]);
                *(float2*)(out + (size_t)BATCH * DH + (size_t)row * DH + c) = make_float2(hn[0], hn[1]);
            }
        }
    }
}

// ---------------- launch ----------------
extern "C" void kernel_launch(void* const* d_in, const int* in_sizes, int n_in,
                              void* d_out, int out_size) {
    (void)in_sizes; (void)n_in; (void)out_size;
    const float* x  = (const float*)d_in[0];
    const float* C  = (const float*)d_in[1];
    const float* h  = (const float*)d_in[2];
    const float* Wx = (const float*)d_in[3];
    const float* bx = (const float*)d_in[4];
    const float* Wh = (const float*)d_in[5];
    const float* bh = (const float*)d_in[6];
    float* out = (float*)d_out;

    static bool attr_set = false;
    if (!attr_set) {
        cudaFuncSetAttribute(lstm_main, cudaFuncAttributeMaxDynamicSharedMemorySize, SMEM_BYTES);
        attr_set = true;
    }

    lstm_prep<<<256, 256>>>(Wx, Wh);

    dim3 grid(DH / WG, BATCH / MT);     // (8 col tiles, 256 row tiles)
    lstm_main<<<grid, THREADS, SMEM_BYTES>>>(x, C, h, bx, bh, out);
}

// round 3
// speedup vs baseline: 1.0431x; 1.0431x over previous
#include <cuda_runtime.h>
#include <cstdint>

#define DEV __device__ __forceinline__

// ---------------- problem constants ----------------
static constexpr int BATCH = 32768;
static constexpr int DH    = 512;          // hidden per gate
static constexpr int KTOT  = 1024;         // D_IN + D_H
static constexpr int MT    = 128;          // rows per CTA
static constexpr int WG    = 64;           // hidden cols per CTA per gate -> N_cta = 256
static constexpr int KC    = 32;           // K chunk
static constexpr int NCHUNK = KTOT / KC;   // 32
static constexpr int THREADS = 256;
static constexpr int STAGES = 4;           // smem buffers (3 cp.async groups in flight)

// smem pitches (words). 36 % 32 == 4 -> LDS.128 conflict-free for both operands.
static constexpr int PA = 36;              // A: [128 rows][32 k] pitch
static constexpr int PB = 36;              // B: [256 cols][32 k] pitch (K-major!)
static constexpr int A_STAGE_B = MT * PA * 4;           // 18432
static constexpr int B_STAGE_B = 256 * PB * 4;          // 36864
static constexpr int STAGE_B   = A_STAGE_B + B_STAGE_B; // 55296
static constexpr uint32_t OFF_BIAS  = STAGES * STAGE_B; // 221184
static constexpr uint32_t SMEM_BYTES = OFF_BIAS + 256 * 4; // 222208

// ---------------- device scratch ----------------
__device__ float g_Wt[4 * DH * KTOT];      // [2048 n][1024 k]  K-major, tf32-rna rounded

// ---------------- PTX helpers ----------------
DEV uint32_t smem_u32(const void* p) {
    uint32_t a;
    asm("{ .reg .u64 t; cvta.to.shared.u64 t, %1; cvt.u32.u64 %0, t; }" : "=r"(a) : "l"(p));
    return a;
}
DEV float tf32_rna(float v) {
    uint32_t u;
    asm("cvt.rna.tf32.f32 %0, %1;" : "=r"(u) : "f"(v));
    return __uint_as_float(u);
}
DEV void cpasync16(uint32_t dst, const void* src) {
    asm volatile("cp.async.cg.shared.global [%0], [%1], 16;" :: "r"(dst), "l"(src));
}
DEV void cp_commit() { asm volatile("cp.async.commit_group;" ::: "memory"); }
template <int N> DEV void cp_wait() { asm volatile("cp.async.wait_group %0;" :: "n"(N) : "memory"); }

DEV void mma_tf32(float& c0, float& c1, float& c2, float& c3,
                  float a0, float a1, float a2, float a3, float b0, float b1) {
    asm volatile(
        "mma.sync.aligned.m16n8k8.row.col.f32.tf32.tf32.f32 "
        "{%0,%1,%2,%3}, {%4,%5,%6,%7}, {%8,%9}, {%0,%1,%2,%3};"
        : "+f"(c0), "+f"(c1), "+f"(c2), "+f"(c3)
        : "r"(__float_as_uint(a0)), "r"(__float_as_uint(a1)),
          "r"(__float_as_uint(a2)), "r"(__float_as_uint(a3)),
          "r"(__float_as_uint(b0)), "r"(__float_as_uint(b1)));
}

DEV float sigm(float z)     { return __fdividef(1.0f, 1.0f + __expf(-z)); }
DEV float tanhfast(float z) { float t = __expf(2.0f * z); return 1.0f - __fdividef(2.0f, t + 1.0f); }

// ---------------- prep: tiled transpose concat(Wx,Wh) -> g_Wt[n][k], tf32-rna ----------------
__global__ void lstm_prep(const float* __restrict__ Wx, const float* __restrict__ Wh) {
    __shared__ float t[32][33];
    const int tx = threadIdx.x, ty = threadIdx.y;           // 32 x 8
    const int nt = blockIdx.x * 32, kt = blockIdx.y * 32;
#pragma unroll
    for (int i = 0; i < 4; i++) {
        int k = kt + ty + i * 8;
        int n = nt + tx;
        float v = (k < 512) ? Wx[(size_t)k * 2048 + n] : Wh[(size_t)(k - 512) * 2048 + n];
        t[ty + i * 8][tx] = tf32_rna(v);
    }
    __syncthreads();
#pragma unroll
    for (int i = 0; i < 4; i++) {
        int n = nt + ty + i * 8;
        int k = kt + tx;
        g_Wt[(size_t)n * KTOT + k] = t[tx][ty + i * 8];
    }
}

// ---------------- main fused kernel ----------------
__global__ __launch_bounds__(THREADS, 1)
void lstm_main(const float* __restrict__ x, const float* __restrict__ Cin,
               const float* __restrict__ h,
               const float* __restrict__ bx, const float* __restrict__ bh,
               float* __restrict__ out) {
    extern __shared__ float smem[];
    const uint32_t sb = smem_u32(smem);

    const int tid  = threadIdx.x;
    const int lane = tid & 31;
    const int wid  = tid >> 5;
    const int tig  = lane & 3;
    const int gid  = lane >> 2;
    const int wm   = wid >> 2;          // 0..1
    const int wn   = wid & 3;           // 0..3

    const int c0 = blockIdx.x * WG;
    const int m0 = blockIdx.y * MT;

    // bias to smem
    {
        int gate = tid >> 6, c = tid & 63;
        int n = gate * DH + c0 + c;
        smem[OFF_BIAS / 4 + tid] = bx[n] + bh[n];
    }

    // ---- async stage loader ----
    auto issue = [&](int ck) {
        const int buf = ck & (STAGES - 1);
        const uint32_t Ao = sb + (uint32_t)(buf * STAGE_B);
        const uint32_t Bo = Ao + A_STAGE_B;
        const int kc0 = ck * KC;
        const float* Abase = (kc0 < 512) ? (x + (size_t)m0 * 512 + kc0)
                                         : (h + (size_t)m0 * 512 + (kc0 - 512));
#pragma unroll
        for (int i = 0; i < 4; i++) {                 // A: 128 rows x 8 x 16B
            int f = tid + i * THREADS;
            int r = f >> 3, j = f & 7;
            cpasync16(Ao + (uint32_t)(r * PA * 4 + j * 16), Abase + (size_t)r * 512 + j * 4);
        }
#pragma unroll
        for (int i = 0; i < 8; i++) {                 // B: 256 cols x 8 x 16B (K-major)
            int f = tid + i * THREADS;
            int cl = f >> 3, j = f & 7;               // cl = gate*64 + cc
            int ng = (cl >> 6) * DH + c0 + (cl & 63); // global n
            cpasync16(Bo + (uint32_t)(cl * PB * 4 + j * 16),
                      g_Wt + (size_t)ng * KTOT + kc0 + j * 4);
        }
    };

    float acc[4][4][2][4];
#pragma unroll
    for (int a = 0; a < 4; a++)
#pragma unroll
        for (int b = 0; b < 4; b++)
#pragma unroll
            for (int hh = 0; hh < 2; hh++)
#pragma unroll
                for (int r = 0; r < 4; r++) acc[a][b][hh][r] = 0.0f;

    issue(0); cp_commit();
    issue(1); cp_commit();
    issue(2); cp_commit();

    for (int ck = 0; ck < NCHUNK; ck++) {
        const int buf = ck & (STAGES - 1);
        const float* Ab = smem + (size_t)buf * (STAGE_B / 4);
        const float* Bb = Ab + A_STAGE_B / 4;

        cp_wait<2>();
        __syncthreads();

#pragma unroll
        for (int half = 0; half < 2; half++) {        // each half covers 2 k8-steps
            // A fragments: 8 x LDS.128
            float4 av[4][2];
#pragma unroll
            for (int mf = 0; mf < 4; mf++)
#pragma unroll
                for (int rh = 0; rh < 2; rh++) {
                    int row = wm * 64 + mf * 16 + rh * 8 + gid;
                    av[mf][rh] = *(const float4*)(Ab + row * PA + tig * 8 + half * 4);
                }
            // B fragments: 8 x LDS.128
            float4 bv[4][2];
#pragma unroll
            for (int gate = 0; gate < 4; gate++)
#pragma unroll
                for (int hh = 0; hh < 2; hh++) {
                    int col = gate * 64 + wn * 16 + hh * 8 + gid;
                    bv[gate][hh] = *(const float4*)(Bb + col * PB + tig * 8 + half * 4);
                }
            // 64 MMAs (2 steps x 32)
#pragma unroll
            for (int s2 = 0; s2 < 2; s2++) {
                const int u = s2 * 2;
#pragma unroll
                for (int mf = 0; mf < 4; mf++) {
                    const float* a0p = &av[mf][0].x;
                    const float* a1p = &av[mf][1].x;
#pragma unroll
                    for (int gate = 0; gate < 4; gate++)
#pragma unroll
                        for (int hh = 0; hh < 2; hh++) {
                            const float* bp = &bv[gate][hh].x;
                            mma_tf32(acc[mf][gate][hh][0], acc[mf][gate][hh][1],
                                     acc[mf][gate][hh][2], acc[mf][gate][hh][3],
                                     a0p[u], a1p[u], a0p[u + 1], a1p[u + 1],
                                     bp[u], bp[u + 1]);
                        }
                }
            }
        }

        if (ck + 3 < NCHUNK) issue(ck + 3);
        cp_commit();
    }

    // ---------------- fused LSTM epilogue ----------------
    const float* biasS = smem + OFF_BIAS / 4;
#pragma unroll
    for (int mf = 0; mf < 4; mf++) {
#pragma unroll
        for (int rh = 0; rh < 2; rh++) {
            const int row = m0 + wm * 64 + mf * 16 + gid + rh * 8;
#pragma unroll
            for (int hh = 0; hh < 2; hh++) {
                const int cl = wn * 16 + hh * 8 + tig * 2;
                const int c  = c0 + cl;
                const float2 cv = *(const float2*)(Cin + (size_t)row * DH + c);
                float cn[2], hn[2];
#pragma unroll
                for (int e = 0; e < 2; e++) {
                    float zi = acc[mf][0][hh][rh * 2 + e] + biasS[0 * 64 + cl + e];
                    float zf = acc[mf][1][hh][rh * 2 + e] + biasS[1 * 64 + cl + e];
                    float zo = acc[mf][2][hh][rh * 2 + e] + biasS[2 * 64 + cl + e];
                    float zg = acc[mf][3][hh][rh * 2 + e] + biasS[3 * 64 + cl + e];
                    float gi = sigm(zi), gf = sigm(zf), go = sigm(zo), gg = tanhfast(zg);
                    float cc = (e == 0) ? cv.x : cv.y;
                    cn[e] = gf * cc + gi * gg;
                    hn[e] = go * tanhfast(cn[e]);
                }
                *(float2*)(out + (size_t)row * DH + c) = make_float2(cn[0], cn[1]);
                *(float2*)(out + (size_t)BATCH * DH + (size_t)row * DH + c) = make_float2(hn[0], hn[1]);
            }
        }
    }
}

// ---------------- launch ----------------
extern "C" void kernel_launch(void* const* d_in, const int* in_sizes, int n_in,
                              void* d_out, int out_size) {
    (void)in_sizes; (void)n_in; (void)out_size;
    const float* x  = (const float*)d_in[0];
    const float* C  = (const float*)d_in[1];
    const float* h  = (const float*)d_in[2];
    const float* Wx = (const float*)d_in[3];
    const float* bx = (const float*)d_in[4];
    const float* Wh = (const float*)d_in[5];
    const float* bh = (const float*)d_in[6];
    float* out = (float*)d_out;

    static bool attr_set = false;
    if (!attr_set) {
        cudaFuncSetAttribute(lstm_main, cudaFuncAttributeMaxDynamicSharedMemorySize, SMEM_BYTES);
        attr_set = true;
    }

    dim3 pgrid(2048 / 32, 1024 / 32);
    dim3 pblk(32, 8);
    lstm_prep<<<pgrid, pblk>>>(Wx, Wh);

    dim3 grid(DH / WG, BATCH / MT);     // (8 col tiles, 256 row tiles)
    lstm_main<<<grid, THREADS, SMEM_BYTES>>>(x, C, h, bx, bh, out);
}